// round 6
// baseline (speedup 1.0000x reference)
#include <cuda_runtime.h>
#include <cstdint>
#include <cstddef>

#define NFEAT 17
#define HDIM 8
#define BSZ 256
#define TSTEPS 512
#define XDIM 59
#define CHK 16
#define NCHK (TSTEPS/CHK)
#define BPC 2
#define NTHREADS 288
#define ROWF 112            // padded floats per (bl,tl) row (16B-aligned slots)

typedef unsigned long long u64;

// Chain-to-slot mapping (slot = warp*4 + group). Heavy warps d-homogeneous:
// w1={f3,f3,f2,f2} (d 13/12), w2={f4,f4,f1,f1} (d 12/8). Others light (d<=2).
__device__ __constant__ int8_t c_slot_f[36] = {
   6, 6, 7, 7,   3, 3, 2, 2,   4, 4, 1, 1,   0, 0, 5, 5,
   8, 8, 9, 9,  10,10,11,11,  12,12,13,13,  14,14,15,15,  16,16,16,16};
__device__ __constant__ int8_t c_slot_b[36] = {
   0, 1, 0, 1,   0, 1, 0, 1,   0, 1, 0, 1,   0, 1, 0, 1,
   0, 1, 0, 1,   0, 1, 0, 1,   0, 1, 0, 1,   0, 1, 0, 1,   0, 1, 0, 1};
__device__ __constant__ int8_t c_slot_wr[36] = {
   1, 1, 1, 1,   1, 1, 1, 1,   1, 1, 1, 1,   1, 1, 1, 1,
   1, 1, 1, 1,   1, 1, 1, 1,   1, 1, 1, 1,   1, 1, 1, 1,   1, 1, 0, 0};
// pairs (of input dims) per warp, warp-uniform
__device__ __constant__ int8_t c_warp_dp[9] = {1,7,6,1,1,1,1,1,1};
// feature -> float offset of its aligned slot within a padded row
__device__ __constant__ int16_t c_foff[17] =
  {56,44,16,0,32, 60,64,68,72,76,80,84,88,92,96,100,104};
// source column s (0..58) -> dst float offset within padded row
__device__ __constant__ int16_t c_dst[59] = {
  56,57,                                         // f0 (d=2)
  44,45,46,47,48,49,50,51,                       // f1 (d=8)
  16,17,18,19,20,21,22,23,24,25,26,27,           // f2 (d=12)
   0, 1, 2, 3, 4, 5, 6, 7, 8, 9,10,11,12,        // f3 (d=13)
  32,33,34,35,36,37,38,39,40,41,42,43,           // f4 (d=12)
  60,64,68,72,76,80,84,88,92,96,100,104};        // f5..f16 (d=1)

template<int N> struct IC { static constexpr int value = N; };

__device__ __forceinline__ float tanh_ap(float x){
  float y; asm("tanh.approx.f32 %0, %1;" : "=f"(y) : "f"(x)); return y;
}
__device__ __forceinline__ u64 pk(float lo, float hi){
  u64 r; asm("mov.b64 %0,{%1,%2};" : "=l"(r) : "f"(lo), "f"(hi)); return r;
}
__device__ __forceinline__ void upk(float& lo, float& hi, u64 p){
  asm("mov.b64 {%0,%1},%2;" : "=f"(lo), "=f"(hi) : "l"(p));
}
__device__ __forceinline__ u64 fma2(u64 a, u64 b, u64 c){
  u64 d; asm("fma.rn.f32x2 %0,%1,%2,%3;" : "=l"(d) : "l"(a), "l"(b), "l"(c)); return d;
}
__device__ __forceinline__ u64 add2(u64 a, u64 b){
  u64 d; asm("add.rn.f32x2 %0,%1,%2;" : "=l"(d) : "l"(a), "l"(b)); return d;
}
__device__ __forceinline__ float hsum(u64 p){
  float lo, hi; upk(lo, hi, p); return lo + hi;
}
__device__ __forceinline__ u64 asu(double d){ return __double_as_longlong(d); }

extern "C" __global__ void __launch_bounds__(NTHREADS, 1)
mcgru_kernel(const float* __restrict__ x,   const float* __restrict__ Wih,
             const float* __restrict__ Whh, const float* __restrict__ bih,
             const float* __restrict__ bhh, float* __restrict__ out)
{
  __shared__ __align__(16) float xs[2][BPC][CHK][ROWF];   // 28.7 KB
  __shared__ __align__(16) float hsm[36][HDIM];           // h exchange

  const int tid  = threadIdx.x;
  const int w    = tid >> 5;
  const int slot = tid >> 3;
  const int j    = tid & 7;
  const int f    = c_slot_f[slot];
  const int bl   = c_slot_b[slot];
  const bool wen = (bool)c_slot_wr[slot];
  const int dp   = c_warp_dp[w];
  const int foff = c_foff[f];
  const int bg0  = blockIdx.x * BPC;

  // ---- zero padded x buffers once (pads stay zero; staging writes data only)
  {
    float4 z = make_float4(0.f,0.f,0.f,0.f);
    float4* p4 = (float4*)&xs[0][0][0][0];
    for (int i = tid; i < (int)(sizeof(xs)/16); i += NTHREADS) p4[i] = z;
  }

  // ---- weights in registers, packed over input/hidden index pairs.
  // r,z paths pre-scaled 0.5 (sigmoid(x)=.5+.5*tanh(x/2)); hh n-path 0.5.
  u64 wrp[7], wzp[7], wnp[7];
  {
    const float* Wf = Wih + f*24*13;
    #pragma unroll
    for (int p = 0; p < 7; ++p){
      int d0 = 2*p, d1 = 2*p + 1;
      float r0 = Wf[(0 + j)*13 + d0], z0 = Wf[(8 + j)*13 + d0], n0 = Wf[(16 + j)*13 + d0];
      float r1 = 0.f, z1 = 0.f, n1 = 0.f;
      if (d1 < 13){ r1 = Wf[(0 + j)*13 + d1]; z1 = Wf[(8 + j)*13 + d1]; n1 = Wf[(16 + j)*13 + d1]; }
      wrp[p] = pk(0.5f*r0, 0.5f*r1);
      wzp[p] = pk(0.5f*z0, 0.5f*z1);
      wnp[p] = pk(n0, n1);
    }
  }
  u64 urp[4], uzp[4], unp[4];
  {
    const float* Uf = Whh + f*24*8;
    #pragma unroll
    for (int p = 0; p < 4; ++p){
      urp[p] = pk(0.5f*Uf[(0 + j)*8 + 2*p], 0.5f*Uf[(0 + j)*8 + 2*p+1]);
      uzp[p] = pk(0.5f*Uf[(8 + j)*8 + 2*p], 0.5f*Uf[(8 + j)*8 + 2*p+1]);
      unp[p] = pk(0.5f*Uf[(16 + j)*8 + 2*p], 0.5f*Uf[(16 + j)*8 + 2*p+1]);
    }
  }
  const u64 brp  = pk(0.5f*(bih[f*24 + j]     + bhh[f*24 + j]),     0.f);
  const u64 bzp  = pk(0.5f*(bih[f*24 + 8 + j] + bhh[f*24 + 8 + j]), 0.f);
  const u64 bxnp = pk(bih[f*24 + 16 + j], 0.f);
  const u64 bhnp = pk(0.5f*bhh[f*24 + 16 + j], 0.f);

  hsm[slot][j] = 0.f;                     // h0 = 0
  __syncthreads();                        // zeros + h init committed

  // ---- staging: 4B cp.async straight into the aligned padded layout.
  // 8 threads per (bl,tl) row, 8 source cols each (last group partial).
  auto stage = [&](int c, int buf){
    int r = tid >> 3;
    if (r < BPC*CHK){
      int sbl = r >> 4, stl = r & (CHK-1);
      const float* src = x + ((size_t)(bg0 + sbl)*TSTEPS + (size_t)c*CHK + stl)*XDIM;
      float* drow = &xs[buf][sbl][stl][0];
      int c0 = j * 8;
      #pragma unroll
      for (int k = 0; k < 8; ++k){
        int s = c0 + k;
        if (s < XDIM){
          uint32_t d = (uint32_t)__cvta_generic_to_shared(drow + c_dst[s]);
          asm volatile("cp.async.ca.shared.global [%0], [%1], 4;" :: "r"(d), "l"(src + s) : "memory");
        }
      }
    }
  };

  stage(0, 0); asm volatile("cp.async.commit_group;" ::: "memory");
  stage(1, 1); asm volatile("cp.async.commit_group;" ::: "memory");

  float h = 0.f;
  float* outp = out + (((size_t)(bg0 + bl)*TSTEPS)*NFEAT + f)*HDIM + j;
  const float* hrow = &hsm[slot][0];
  float* hst = &hsm[slot][j];

  auto run_chunk = [&](auto DPc, const float* xbase, float* outc){
    constexpr int DP = decltype(DPc)::value;
    #pragma unroll 2
    for (int tl = 0; tl < CHK; ++tl){
      // ---- gx: aligned vector loads feed fma2 directly (no packing movs)
      const double* xp = (const double*)(xbase + tl*ROWF);
      u64 X[8];
      if constexpr (DP == 1){
        X[0] = asu(xp[0]);
      } else {
        constexpr int NQ = (DP + 1)/2;
        const double2* xq = (const double2*)xp;
        #pragma unroll
        for (int q = 0; q < NQ; ++q){
          double2 v = xq[q];
          X[2*q] = asu(v.x); X[2*q+1] = asu(v.y);
        }
      }
      u64 gr = brp, gz = bzp, gn = bxnp;
      #pragma unroll
      for (int p = 0; p < DP; ++p){
        gr = fma2(wrp[p], X[p], gr);
        gz = fma2(wzp[p], X[p], gz);
        gn = fma2(wnp[p], X[p], gn);
      }
      // ---- h exchange: previous step's STS is many instrs back
      __syncwarp();
      u64 H[4];
      {
        const double2* hq = (const double2*)hrow;
        double2 a = hq[0], b = hq[1];
        H[0] = asu(a.x); H[1] = asu(a.y); H[2] = asu(b.x); H[3] = asu(b.y);
      }
      u64 hr = 0ULL, hz = 0ULL, hn = bhnp;
      #pragma unroll
      for (int p = 0; p < 4; ++p){
        hr = fma2(urp[p], H[p], hr);
        hz = fma2(uzp[p], H[p], hz);
        hn = fma2(unp[p], H[p], hn);
      }
      // ---- gates (tanh-form; halves pre-folded into weights)
      float tr  = tanh_ap(hsum(add2(gr, hr)));
      float tz  = tanh_ap(hsum(add2(gz, hz)));
      float hnh = hsum(hn);                    // 0.5*(Un h + bhn)
      float s   = hsum(add2(gn, hn));          // gn + hnh
      float a   = fmaf(tr, hnh, s);            // gn + r*(Un h + bhn)
      float n   = tanh_ap(a);
      float u   = 0.5f*(h - n);
      h = fmaf(tz, u, n + u);                  // (1-z)*n + z*h
      *hst = h;                                // publish for next step
      if (wen) outc[(size_t)tl*(NFEAT*HDIM)] = h;
    }
  };

  for (int c = 0; c < NCHK; ++c){
    asm volatile("cp.async.wait_group 1;" ::: "memory");
    __syncthreads();
    // THE FIX: per-feature slot offset folded into the chunk base pointer.
    const float* xbase = &xs[c & 1][bl][0][0] + foff;
    float* outc = outp + (size_t)c*CHK*(NFEAT*HDIM);

    if (dp == 7)      run_chunk(IC<7>{}, xbase, outc);
    else if (dp == 6) run_chunk(IC<6>{}, xbase, outc);
    else              run_chunk(IC<1>{}, xbase, outc);

    __syncthreads();
    if (c + 2 < NCHK) stage(c + 2, c & 1);
    asm volatile("cp.async.commit_group;" ::: "memory");
  }
}

extern "C" void kernel_launch(void* const* d_in, const int* in_sizes, int n_in,
                              void* d_out, int out_size)
{
  const float* x   = (const float*)d_in[0];
  const float* Wih = (const float*)d_in[1];
  const float* Whh = (const float*)d_in[2];
  const float* bih = (const float*)d_in[3];
  const float* bhh = (const float*)d_in[4];
  (void)in_sizes; (void)n_in; (void)out_size;
  mcgru_kernel<<<BSZ/BPC, NTHREADS>>>(x, Wih, Whh, bih, bhh, (float*)d_out);
}